// round 7
// baseline (speedup 1.0000x reference)
#include <cuda_runtime.h>
#include <cuda_bf16.h>

#define NN 100000
#define EE 1600000
#define TOT_EDGES (EE + NN)   // edges + self loops

// ---------------- scratch (no allocation allowed) ----------------
__device__ float g_h1[NN * 128];
__device__ float g_h2[NN * 128];
__device__ float g_xcomb[NN * 256];
__device__ float g_as1[NN * 2];
__device__ float g_ad1[NN * 2];
__device__ float g_as2[NN * 2];
__device__ float g_ad2[NN * 2];
__device__ int   g_cnt[NN];
__device__ int   g_offs[NN + 1];
__device__ int   g_cur[NN];
__device__ int   g_csr[TOT_EDGES];

// ---------------- f32x2 packed helpers (sm_100+) ----------------
__device__ __forceinline__ unsigned long long pack2(float x) {
    unsigned long long r;
    asm("mov.b64 %0, {%1, %1};" : "=l"(r) : "f"(x));
    return r;
}
__device__ __forceinline__ void ffma2(unsigned long long& d,
                                      unsigned long long a,
                                      unsigned long long b) {
    asm("fma.rn.f32x2 %0, %1, %2, %0;" : "+l"(d) : "l"(a), "l"(b));
}
__device__ __forceinline__ float2 unpack2(unsigned long long u) {
    float2 f;
    asm("mov.b64 {%0, %1}, %2;" : "=f"(f.x), "=f"(f.y) : "l"(u));
    return f;
}

// ---------------- GEMM: C[M,Nf] = A[M,K] @ B[K,Nf] (+bias) ----------------
// BM=128, BN=64, BK=32, 256 threads, per-thread 8x4 via f32x2 pairs along M.
// As stored transposed [k][m] with an 8-float-block XOR swizzle to keep both
// the STS (A-tile fill) and the LDS (ulonglong2 a-frag) near conflict-free.
#define ASWZ(k, m) ((k)*128 + (((((m) >> 3) ^ (((k) >> 2) & 3))) << 3) + ((m) & 7))

__global__ __launch_bounds__(256, 2) void gemm_kernel(
    const float* __restrict__ A, const float* __restrict__ B,
    const float* __restrict__ bias, float* __restrict__ C,
    int M, int Nf, int K)
{
    __shared__ float As_f[32 * 128];
    __shared__ float Bs[32][64];

    const int tid = threadIdx.x;
    const int tx = tid & 15;          // N direction (4 cols)
    const int ty = tid >> 4;          // M direction (8 rows)
    const int m0 = blockIdx.x * 128;
    const int n0 = blockIdx.y * 64;

    unsigned long long acc[4][4];
#pragma unroll
    for (int i = 0; i < 4; i++)
#pragma unroll
        for (int j = 0; j < 4; j++) acc[i][j] = 0ull;

    for (int k0 = 0; k0 < K; k0 += 32) {
        // A tile: 128 rows x 32 k  (1024 float4, 4 per thread), coalesced along k
#pragma unroll
        for (int i = 0; i < 4; i++) {
            int p = i * 256 + tid;
            int row = p >> 3;
            int c4 = p & 7;
            int gm = m0 + row;
            float4 v = make_float4(0.f, 0.f, 0.f, 0.f);
            if (gm < M) v = *(const float4*)&A[(size_t)gm * K + k0 + c4 * 4];
            int kk = c4 * 4;
            As_f[ASWZ(kk + 0, row)] = v.x;
            As_f[ASWZ(kk + 1, row)] = v.y;
            As_f[ASWZ(kk + 2, row)] = v.z;
            As_f[ASWZ(kk + 3, row)] = v.w;
        }
        // B tile: 32 k x 64 n (512 float4, 2 per thread)
#pragma unroll
        for (int i = 0; i < 2; i++) {
            int p = i * 256 + tid;
            int row = p >> 4;
            int c4 = p & 15;
            float4 v = *(const float4*)&B[(size_t)(k0 + row) * Nf + n0 + c4 * 4];
            *(float4*)&Bs[row][c4 * 4] = v;
        }
        __syncthreads();

#pragma unroll
        for (int k = 0; k < 32; k++) {
            int abase = k * 128 + (((ty ^ ((k >> 2) & 3)) << 3));
            ulonglong2 a01 = *(const ulonglong2*)&As_f[abase];
            ulonglong2 a23 = *(const ulonglong2*)&As_f[abase + 4];
            float4 bv = *(const float4*)&Bs[k][tx * 4];
            unsigned long long b0 = pack2(bv.x);
            unsigned long long b1 = pack2(bv.y);
            unsigned long long b2 = pack2(bv.z);
            unsigned long long b3 = pack2(bv.w);
            ffma2(acc[0][0], a01.x, b0); ffma2(acc[0][1], a01.x, b1);
            ffma2(acc[0][2], a01.x, b2); ffma2(acc[0][3], a01.x, b3);
            ffma2(acc[1][0], a01.y, b0); ffma2(acc[1][1], a01.y, b1);
            ffma2(acc[1][2], a01.y, b2); ffma2(acc[1][3], a01.y, b3);
            ffma2(acc[2][0], a23.x, b0); ffma2(acc[2][1], a23.x, b1);
            ffma2(acc[2][2], a23.x, b2); ffma2(acc[2][3], a23.x, b3);
            ffma2(acc[3][0], a23.y, b0); ffma2(acc[3][1], a23.y, b1);
            ffma2(acc[3][2], a23.y, b2); ffma2(acc[3][3], a23.y, b3);
        }
        __syncthreads();
    }

    float4 bvv = make_float4(0.f, 0.f, 0.f, 0.f);
    if (bias) bvv = *(const float4*)&bias[n0 + tx * 4];

#pragma unroll
    for (int i = 0; i < 4; i++) {
        float2 v0 = unpack2(acc[i][0]);
        float2 v1 = unpack2(acc[i][1]);
        float2 v2 = unpack2(acc[i][2]);
        float2 v3 = unpack2(acc[i][3]);
        int r0 = m0 + ty * 8 + 2 * i;
        if (r0 < M) {
            float4 o = make_float4(v0.x + bvv.x, v1.x + bvv.y, v2.x + bvv.z, v3.x + bvv.w);
            *(float4*)&C[(size_t)r0 * Nf + n0 + tx * 4] = o;
        }
        if (r0 + 1 < M) {
            float4 o = make_float4(v0.y + bvv.x, v1.y + bvv.y, v2.y + bvv.z, v3.y + bvv.w);
            *(float4*)&C[(size_t)(r0 + 1) * Nf + n0 + tx * 4] = o;
        }
    }
}

// ---------------- attention coefficients ----------------
// one warp per node; handles both layers. a_src[n,h] = sum_c h[n,h,c]*att_src[h,c]
__global__ __launch_bounds__(256) void acoef_kernel(
    const float* __restrict__ h1, const float* __restrict__ h2,
    const float* __restrict__ as1, const float* __restrict__ ad1,
    const float* __restrict__ as2, const float* __restrict__ ad2,
    float* __restrict__ oas1, float* __restrict__ oad1,
    float* __restrict__ oas2, float* __restrict__ oad2)
{
    int node = (blockIdx.x * blockDim.x + threadIdx.x) >> 5;
    if (node >= NN) return;
    int lane = threadIdx.x & 31;
    int hl = lane >> 4;

#pragma unroll
    for (int L = 0; L < 2; L++) {
        const float* h = (L == 0) ? h1 : h2;
        const float* ats = (L == 0) ? as1 : as2;
        const float* atd = (L == 0) ? ad1 : ad2;
        float* oas = (L == 0) ? oas1 : oas2;
        float* oad = (L == 0) ? oad1 : oad2;

        float4 hv = *(const float4*)&h[(size_t)node * 128 + lane * 4];
        float4 sv = *(const float4*)&ats[lane * 4];
        float4 dv = *(const float4*)&atd[lane * 4];
        float ps = hv.x * sv.x + hv.y * sv.y + hv.z * sv.z + hv.w * sv.w;
        float pd = hv.x * dv.x + hv.y * dv.y + hv.z * dv.z + hv.w * dv.w;
#pragma unroll
        for (int o = 8; o > 0; o >>= 1) {
            ps += __shfl_xor_sync(0xffffffffu, ps, o);
            pd += __shfl_xor_sync(0xffffffffu, pd, o);
        }
        if ((lane & 15) == 0) {
            oas[node * 2 + hl] = ps;
            oad[node * 2 + hl] = pd;
        }
    }
}

// ---------------- CSR build ----------------
__global__ void init_cnt_kernel(int* __restrict__ cnt) {
    int i = blockIdx.x * blockDim.x + threadIdx.x;
    if (i < NN) cnt[i] = 1;  // self loop
}

__global__ void count_edges_kernel(const int* __restrict__ ei, int* __restrict__ cnt) {
    int j = blockIdx.x * blockDim.x + threadIdx.x;
    if (j < EE) atomicAdd(&cnt[ei[EE + j]], 1);
}

// single-block exclusive scan of cnt[NN] -> offs[NN+1], also copies into cur
__global__ __launch_bounds__(1024) void scan_kernel(
    const int* __restrict__ cnt, int* __restrict__ offs, int* __restrict__ cur)
{
    __shared__ int sums[1024];
    const int CH = (NN + 1023) / 1024;  // 98
    int t = threadIdx.x;
    int base = t * CH;
    int local = 0;
    for (int i = 0; i < CH; i++) {
        int idx = base + i;
        if (idx < NN) local += cnt[idx];
    }
    sums[t] = local;
    __syncthreads();
#pragma unroll
    for (int off = 1; off < 1024; off <<= 1) {
        int v = (t >= off) ? sums[t - off] : 0;
        __syncthreads();
        sums[t] += v;
        __syncthreads();
    }
    int run = sums[t] - local;  // exclusive prefix
    for (int i = 0; i < CH; i++) {
        int idx = base + i;
        if (idx < NN) {
            offs[idx] = run;
            cur[idx] = run;
            run += cnt[idx];
        }
    }
    if (base < NN && base + CH >= NN) offs[NN] = run;
}

__global__ void fill_edges_kernel(const int* __restrict__ ei,
                                  int* __restrict__ cur, int* __restrict__ csr) {
    int j = blockIdx.x * blockDim.x + threadIdx.x;
    if (j >= TOT_EDGES) return;
    int s, d;
    if (j < EE) { s = ei[j]; d = ei[EE + j]; }
    else        { s = d = j - EE; }
    int pos = atomicAdd(&cur[d], 1);
    csr[pos] = s;
}

// ---------------- aggregation: one warp per dst node ----------------
// lanes 0-15 -> head 0, lanes 16-31 -> head 1; each lane owns 4 channels.
// two-pass softmax (local max, then exp/sum + weighted gather of h[src]).
__global__ __launch_bounds__(256) void agg_kernel(
    const float* __restrict__ h, const float* __restrict__ asrc,
    const float* __restrict__ adst, const int* __restrict__ offs,
    const int* __restrict__ csr, const float* __restrict__ bias,
    float* __restrict__ xcomb, int colOff)
{
    int node = (blockIdx.x * blockDim.x + threadIdx.x) >> 5;
    if (node >= NN) return;
    int lane = threadIdx.x & 31;
    int hl = lane >> 4;
    int c4 = (lane & 15) * 4;

    float ad = adst[node * 2 + hl];
    int beg = offs[node];
    int end = offs[node + 1];

    float mx = -1e30f;
    for (int j = beg; j < end; ++j) {
        int s = csr[j];
        float e = asrc[s * 2 + hl] + ad;
        e = (e > 0.f) ? e : 0.2f * e;
        mx = fmaxf(mx, e);
    }

    float sum = 0.f;
    float4 acc = make_float4(0.f, 0.f, 0.f, 0.f);
    for (int j = beg; j < end; ++j) {
        int s = csr[j];
        float e = asrc[s * 2 + hl] + ad;
        e = (e > 0.f) ? e : 0.2f * e;
        float p = __expf(e - mx);
        sum += p;
        float4 hv = *(const float4*)&h[(size_t)s * 128 + hl * 64 + c4];
        acc.x = fmaf(hv.x, p, acc.x);
        acc.y = fmaf(hv.y, p, acc.y);
        acc.z = fmaf(hv.z, p, acc.z);
        acc.w = fmaf(hv.w, p, acc.w);
    }

    float inv = 1.f / sum;
    float4 bv = *(const float4*)&bias[hl * 64 + c4];
    float4 r;
    r.x = fmaxf(fmaf(acc.x, inv, bv.x), 0.f);
    r.y = fmaxf(fmaf(acc.y, inv, bv.y), 0.f);
    r.z = fmaxf(fmaf(acc.z, inv, bv.z), 0.f);
    r.w = fmaxf(fmaf(acc.w, inv, bv.w), 0.f);
    *(float4*)&xcomb[(size_t)node * 256 + colOff + hl * 64 + c4] = r;
}

// ---------------- launch ----------------
extern "C" void kernel_launch(void* const* d_in, const int* in_sizes, int n_in,
                              void* d_out, int out_size) {
    const float* x    = (const float*)d_in[0];
    const int*   eic  = (const int*)d_in[1];
    const int*   eil  = (const int*)d_in[2];
    const float* W1   = (const float*)d_in[3];
    const float* as1  = (const float*)d_in[4];
    const float* ad1  = (const float*)d_in[5];
    const float* b1   = (const float*)d_in[6];
    const float* W2   = (const float*)d_in[7];
    const float* as2  = (const float*)d_in[8];
    const float* ad2  = (const float*)d_in[9];
    const float* b2   = (const float*)d_in[10];
    const float* fcW  = (const float*)d_in[11];
    const float* fcb  = (const float*)d_in[12];
    float* out = (float*)d_out;

    float *h1, *h2, *xcomb, *pas1, *pad1, *pas2, *pad2;
    int *cnt, *offs, *cur, *csr;
    cudaGetSymbolAddress((void**)&h1, g_h1);
    cudaGetSymbolAddress((void**)&h2, g_h2);
    cudaGetSymbolAddress((void**)&xcomb, g_xcomb);
    cudaGetSymbolAddress((void**)&pas1, g_as1);
    cudaGetSymbolAddress((void**)&pad1, g_ad1);
    cudaGetSymbolAddress((void**)&pas2, g_as2);
    cudaGetSymbolAddress((void**)&pad2, g_ad2);
    cudaGetSymbolAddress((void**)&cnt, g_cnt);
    cudaGetSymbolAddress((void**)&offs, g_offs);
    cudaGetSymbolAddress((void**)&cur, g_cur);
    cudaGetSymbolAddress((void**)&csr, g_csr);

    const int M = NN, K = 256;
    dim3 gH((M + 127) / 128, 2);   // Nf = 128
    dim3 gF((M + 127) / 128, 1);   // Nf = 64

    // feature transforms
    gemm_kernel<<<gH, 256>>>(x, W1, nullptr, h1, M, 128, K);
    gemm_kernel<<<gH, 256>>>(x, W2, nullptr, h2, M, 128, K);
    acoef_kernel<<<(NN * 32 + 255) / 256, 256>>>(h1, h2, as1, ad1, as2, ad2,
                                                 pas1, pad1, pas2, pad2);

    const int cntBlocks  = (NN + 255) / 256;
    const int edgeBlocks = (EE + 255) / 256;
    const int fillBlocks = (TOT_EDGES + 255) / 256;
    const int aggBlocks  = (NN * 32 + 255) / 256;

    // layer 1 (connected)
    init_cnt_kernel<<<cntBlocks, 256>>>(cnt);
    count_edges_kernel<<<edgeBlocks, 256>>>(eic, cnt);
    scan_kernel<<<1, 1024>>>(cnt, offs, cur);
    fill_edges_kernel<<<fillBlocks, 256>>>(eic, cur, csr);
    agg_kernel<<<aggBlocks, 256>>>(h1, pas1, pad1, offs, csr, b1, xcomb, 0);

    // layer 2 (liked)
    init_cnt_kernel<<<cntBlocks, 256>>>(cnt);
    count_edges_kernel<<<edgeBlocks, 256>>>(eil, cnt);
    scan_kernel<<<1, 1024>>>(cnt, offs, cur);
    fill_edges_kernel<<<fillBlocks, 256>>>(eil, cur, csr);
    agg_kernel<<<aggBlocks, 256>>>(h2, pas2, pad2, offs, csr, b2, xcomb, 128);

    // final FC
    gemm_kernel<<<gF, 256>>>(xcomb, fcW, fcb, out, M, 64, K);
}

// round 10
// speedup vs baseline: 1.6247x; 1.6247x over previous
#include <cuda_runtime.h>
#include <cuda_bf16.h>
#include <cstdint>

#define NN 100000
#define EE 1600000

// ---------------- scratch (no allocation allowed) ----------------
__device__ float g_h1[NN * 128];
__device__ float g_h2[NN * 128];
__device__ float g_xcomb[NN * 256];
__device__ float g_as1[NN * 2];
__device__ float g_ad1[NN * 2];
__device__ float g_as2[NN * 2];
__device__ float g_ad2[NN * 2];
__device__ int   g_cnt[2 * NN];
__device__ int   g_offs[2 * (NN + 1)];
__device__ int   g_cur[2 * NN];
__device__ int   g_csr[2 * EE];
// W^T bf16, TWO images per weight: hi at [0, NF*256), lo at [NF*256, NF*512)
// each image chunk-major swizzled: chunk kc=k>>6, row n, 16B-unit u=(k&63)>>3
__device__ __align__(16) __nv_bfloat16 g_w1[128 * 512];
__device__ __align__(16) __nv_bfloat16 g_w2[128 * 512];
__device__ __align__(16) __nv_bfloat16 g_wf[64 * 512];

// ---------------- helpers ----------------
__device__ __forceinline__ uint32_t smem_to_u32(const void* p) {
    uint32_t a;
    asm("{ .reg .u64 t; cvta.to.shared.u64 t, %1; cvt.u32.u64 %0, t; }" : "=r"(a) : "l"(p));
    return a;
}
__device__ __forceinline__ void ldmatrix_x4(uint32_t* r, uint32_t addr) {
    asm volatile("ldmatrix.sync.aligned.m8n8.x4.shared.b16 {%0,%1,%2,%3}, [%4];"
        : "=r"(r[0]), "=r"(r[1]), "=r"(r[2]), "=r"(r[3]) : "r"(addr));
}
__device__ __forceinline__ void ldmatrix_x2(uint32_t* r, uint32_t addr) {
    asm volatile("ldmatrix.sync.aligned.m8n8.x2.shared.b16 {%0,%1}, [%2];"
        : "=r"(r[0]), "=r"(r[1]) : "r"(addr));
}
__device__ __forceinline__ void mma16816(float* c, const uint32_t* a, const uint32_t* b) {
    asm volatile(
        "mma.sync.aligned.m16n8k16.row.col.f32.bf16.bf16.f32 "
        "{%0,%1,%2,%3},{%4,%5,%6,%7},{%8,%9},{%0,%1,%2,%3};"
        : "+f"(c[0]), "+f"(c[1]), "+f"(c[2]), "+f"(c[3])
        : "r"(a[0]), "r"(a[1]), "r"(a[2]), "r"(a[3]), "r"(b[0]), "r"(b[1]));
}
__device__ __forceinline__ void cp_async16(uint32_t dst, const void* src) {
    asm volatile("cp.async.cg.shared.global [%0], [%1], 16;" :: "r"(dst), "l"(src));
}
__device__ __forceinline__ uint32_t bf2bits(__nv_bfloat162 v) {
    return *reinterpret_cast<uint32_t*>(&v);
}

// ---------------- W prep: [K,NF] fp32 -> hi image + lo image (swizzled) ----------------
__global__ void prep_w_kernel(const float* __restrict__ W1, const float* __restrict__ W2,
                              const float* __restrict__ Wf,
                              __nv_bfloat16* o1, __nv_bfloat16* o2, __nv_bfloat16* of)
{
    int idx = blockIdx.x * blockDim.x + threadIdx.x;
    const float* W; __nv_bfloat16* o; int NF, id;
    if (idx < 32768)      { W = W1; o = o1; NF = 128; id = idx; }
    else if (idx < 65536) { W = W2; o = o2; NF = 128; id = idx - 32768; }
    else if (idx < 81920) { W = Wf; o = of; NF = 64;  id = idx - 65536; }
    else return;
    int n = id % NF, k = id / NF;
    float v = W[id];
    __nv_bfloat16 hi = __float2bfloat16_rn(v);
    __nv_bfloat16 lo = __float2bfloat16_rn(v - __bfloat162float(hi));
    uint32_t b = (uint32_t)((k >> 6) * NF + n) * 128u
               + (uint32_t)((((k & 63) >> 3) ^ (n & 7)) << 4) + (uint32_t)(k & 7) * 2u;
    *(__nv_bfloat16*)((char*)o + b) = hi;
    *(__nv_bfloat16*)((char*)(o + NF * 256) + b) = lo;
}

// ---------------- bf16 mma GEMM with 3-product hi/lo compensation ----------------
// C = A@W computed as Ahi*Whi + Ahi*Wlo + Alo*Whi (err ~1e-5).
// Persistent 148 CTAs; W hi+lo fully smem-resident; A chunks (64 k) double buffered.
template <int NF, bool BIAS>
__global__ __launch_bounds__(256) void gemm_mma_kernel(
    const float* __restrict__ A, const __nv_bfloat16* __restrict__ Wt,
    const float* __restrict__ bias, float* __restrict__ C, int M, int numTiles)
{
    constexpr int NT = NF / 16;          // n-tiles per warp (warp grid 4x2)
    constexpr int WIMG = NF * 512;       // bytes per W image (4 chunks * NF * 128B)
    constexpr int OFF_A = 2 * WIMG;      // A: per buf {hi 16KB, lo 16KB}

    extern __shared__ __align__(16) char smem[];
    const uint32_t sb = smem_to_u32(smem);
    const int tid = threadIdx.x, wid = tid >> 5, lane = tid & 31;
    const int wm = wid & 3, wn = wid >> 2;
    const int wnb = wn * (NF / 2);

    // load both W images (already in final layout) into smem once
    for (int i = tid; i < NF * 64; i += 256)
        cp_async16(sb + (uint32_t)i * 16u, ((const uint4*)Wt) + i);
    asm volatile("cp.async.commit_group;");
    asm volatile("cp.async.wait_group 0;");
    __syncthreads();

    const int r15 = lane & 15, rh = lane >> 4;
    float4 pa[8];

    for (int tile = blockIdx.x; tile < numTiles; tile += gridDim.x) {
        const int m0 = tile * 128;
        float acc[2][NT][4];
#pragma unroll
        for (int mt = 0; mt < 2; mt++)
#pragma unroll
            for (int nt = 0; nt < NT; nt++)
#pragma unroll
                for (int q = 0; q < 4; q++) acc[mt][nt][q] = 0.f;

        // prefetch chunk 0 (128 rows x 64 fp32)
#pragma unroll
        for (int i = 0; i < 8; i++) {
            int p = i * 256 + tid, row = p >> 4, c4 = p & 15, gm = m0 + row;
            pa[i] = (gm < M) ? *(const float4*)&A[(size_t)gm * 256 + c4 * 4]
                             : make_float4(0.f, 0.f, 0.f, 0.f);
        }

#pragma unroll
        for (int kc = 0; kc < 4; kc++) {
            const int buf = kc & 1;
            const uint32_t aOff = OFF_A + (uint32_t)buf * 32768u;
            // store A chunk: hi image + lo image, swizzled
#pragma unroll
            for (int i = 0; i < 8; i++) {
                int p = i * 256 + tid, row = p >> 4, c4 = p & 15;
                float4 v = pa[i];
                __nv_bfloat16 h0 = __float2bfloat16_rn(v.x);
                __nv_bfloat16 h1 = __float2bfloat16_rn(v.y);
                __nv_bfloat16 h2 = __float2bfloat16_rn(v.z);
                __nv_bfloat16 h3 = __float2bfloat16_rn(v.w);
                __nv_bfloat16 l0 = __float2bfloat16_rn(v.x - __bfloat162float(h0));
                __nv_bfloat16 l1 = __float2bfloat16_rn(v.y - __bfloat162float(h1));
                __nv_bfloat16 l2 = __float2bfloat16_rn(v.z - __bfloat162float(h2));
                __nv_bfloat16 l3 = __float2bfloat16_rn(v.w - __bfloat162float(h3));
                int u = c4 >> 1, half = (c4 & 1) * 8;
                uint32_t base = (uint32_t)row * 128u +
                                (uint32_t)((u ^ (row & 7)) << 4) + (uint32_t)half;
                *(uint2*)(smem + aOff + base) =
                    make_uint2(bf2bits(__halves2bfloat162(h0, h1)),
                               bf2bits(__halves2bfloat162(h2, h3)));
                *(uint2*)(smem + aOff + 16384u + base) =
                    make_uint2(bf2bits(__halves2bfloat162(l0, l1)),
                               bf2bits(__halves2bfloat162(l2, l3)));
            }
            __syncthreads();

            // prefetch next chunk (overlaps mma)
            if (kc < 3) {
#pragma unroll
                for (int i = 0; i < 8; i++) {
                    int p = i * 256 + tid, row = p >> 4, c4 = p & 15, gm = m0 + row;
                    pa[i] = (gm < M)
                        ? *(const float4*)&A[(size_t)gm * 256 + (kc + 1) * 64 + c4 * 4]
                        : make_float4(0.f, 0.f, 0.f, 0.f);
                }
            }

            const uint32_t aH = sb + aOff;
            const uint32_t aL = aH + 16384u;
            const uint32_t bH = sb + (uint32_t)kc * (NF * 128u);
            const uint32_t bL = bH + (uint32_t)WIMG;
#pragma unroll
            for (int k16 = 0; k16 < 4; k16++) {
                uint32_t ah[2][4], al[2][4];
#pragma unroll
                for (int mt = 0; mt < 2; mt++) {
                    int row = wm * 32 + mt * 16 + r15;
                    uint32_t off = (uint32_t)row * 128u +
                                   (uint32_t)(((k16 * 2 + rh) ^ (row & 7)) << 4);
                    ldmatrix_x4(ah[mt], aH + off);
                    ldmatrix_x4(al[mt], aL + off);
                }
#pragma unroll
                for (int nt = 0; nt < NT; nt++) {
                    int rn = wnb + nt * 8 + (lane & 7);
                    int un = k16 * 2 + ((lane >> 3) & 1);
                    uint32_t off = (uint32_t)rn * 128u +
                                   (uint32_t)((un ^ (rn & 7)) << 4);
                    uint32_t bh[2], bl[2];
                    ldmatrix_x2(bh, bH + off);
                    ldmatrix_x2(bl, bL + off);
#pragma unroll
                    for (int mt = 0; mt < 2; mt++) {
                        mma16816(acc[mt][nt], ah[mt], bh);
                        mma16816(acc[mt][nt], ah[mt], bl);
                        mma16816(acc[mt][nt], al[mt], bh);
                    }
                }
            }
            __syncthreads();
        }

        // epilogue: direct coalesced stores
#pragma unroll
        for (int nt = 0; nt < NT; nt++) {
            int col = wnb + nt * 8 + (lane & 3) * 2;
            float bx = 0.f, by = 0.f;
            if (BIAS) { bx = bias[col]; by = bias[col + 1]; }
#pragma unroll
            for (int mt = 0; mt < 2; mt++) {
                int row = m0 + wm * 32 + mt * 16 + (lane >> 2);
                if (row < M) {
                    float2 o = make_float2(acc[mt][nt][0] + bx, acc[mt][nt][1] + by);
                    *(float2*)&C[(size_t)row * NF + col] = o;
                }
                if (row + 8 < M) {
                    float2 o = make_float2(acc[mt][nt][2] + bx, acc[mt][nt][3] + by);
                    *(float2*)&C[(size_t)(row + 8) * NF + col] = o;
                }
            }
        }
    }
}

// ---------------- attention coefficients (one warp per node, both layers) ----------------
__global__ __launch_bounds__(256) void acoef_kernel(
    const float* __restrict__ h1, const float* __restrict__ h2,
    const float* __restrict__ as1, const float* __restrict__ ad1,
    const float* __restrict__ as2, const float* __restrict__ ad2,
    float* __restrict__ oas1, float* __restrict__ oad1,
    float* __restrict__ oas2, float* __restrict__ oad2)
{
    int node = (blockIdx.x * blockDim.x + threadIdx.x) >> 5;
    if (node >= NN) return;
    int lane = threadIdx.x & 31;
    int hl = lane >> 4;

#pragma unroll
    for (int L = 0; L < 2; L++) {
        const float* h = (L == 0) ? h1 : h2;
        const float* ats = (L == 0) ? as1 : as2;
        const float* atd = (L == 0) ? ad1 : ad2;
        float* oas = (L == 0) ? oas1 : oas2;
        float* oad = (L == 0) ? oad1 : oad2;

        float4 hv = *(const float4*)&h[(size_t)node * 128 + lane * 4];
        float4 sv = *(const float4*)&ats[lane * 4];
        float4 dv = *(const float4*)&atd[lane * 4];
        float ps = hv.x * sv.x + hv.y * sv.y + hv.z * sv.z + hv.w * sv.w;
        float pd = hv.x * dv.x + hv.y * dv.y + hv.z * dv.z + hv.w * dv.w;
#pragma unroll
        for (int o = 8; o > 0; o >>= 1) {
            ps += __shfl_xor_sync(0xffffffffu, ps, o);
            pd += __shfl_xor_sync(0xffffffffu, pd, o);
        }
        if ((lane & 15) == 0) {
            oas[node * 2 + hl] = ps;
            oad[node * 2 + hl] = pd;
        }
    }
}

// ---------------- CSR build (both layers fused, no self loops in CSR) ----------------
__global__ void count2_kernel(const int* __restrict__ eic, const int* __restrict__ eil,
                              int* __restrict__ cnt) {
    int j = blockIdx.x * blockDim.x + threadIdx.x;
    if (j < EE)          atomicAdd(&cnt[eic[EE + j]], 1);
    else if (j < 2 * EE) atomicAdd(&cnt[NN + eil[EE + (j - EE)]], 1);
}

__global__ __launch_bounds__(1024) void scan2_kernel(
    const int* __restrict__ cntA, int* __restrict__ offsA, int* __restrict__ curA)
{
    const int L = blockIdx.x;
    const int* cnt = cntA + L * NN;
    int* offs = offsA + L * (NN + 1);
    int* cur  = curA + L * NN;

    __shared__ int sums[1024];
    const int CH = (NN + 1023) / 1024;
    int t = threadIdx.x;
    int base = t * CH;
    int local = 0;
    for (int i = 0; i < CH; i++) {
        int idx = base + i;
        if (idx < NN) local += cnt[idx];
    }
    sums[t] = local;
    __syncthreads();
#pragma unroll
    for (int off = 1; off < 1024; off <<= 1) {
        int v = (t >= off) ? sums[t - off] : 0;
        __syncthreads();
        sums[t] += v;
        __syncthreads();
    }
    int run = sums[t] - local;
    for (int i = 0; i < CH; i++) {
        int idx = base + i;
        if (idx < NN) {
            offs[idx] = run;
            cur[idx] = run;
            run += cnt[idx];
        }
    }
    if (base < NN && base + CH >= NN) offs[NN] = run;
}

__global__ void fill2_kernel(const int* __restrict__ eic, const int* __restrict__ eil,
                             int* __restrict__ cur, int* __restrict__ csr) {
    int j = blockIdx.x * blockDim.x + threadIdx.x;
    if (j >= 2 * EE) return;
    const int* ei; int* cu; int* cs; int e;
    if (j < EE) { ei = eic; cu = cur;      cs = csr;      e = j; }
    else        { ei = eil; cu = cur + NN; cs = csr + EE; e = j - EE; }
    int s = ei[e], d = ei[EE + e];
    int pos = atomicAdd(&cu[d], 1);
    cs[pos] = s;
}

// ---------------- aggregation: one warp per dst, single-pass softmax ----------------
__global__ __launch_bounds__(256) void agg_kernel(
    const float* __restrict__ h, const float* __restrict__ asrc,
    const float* __restrict__ adst, const int* __restrict__ offs,
    const int* __restrict__ csr, const float* __restrict__ bias,
    float* __restrict__ xcomb, int colOff)
{
    int node = (blockIdx.x * blockDim.x + threadIdx.x) >> 5;
    if (node >= NN) return;
    int lane = threadIdx.x & 31;
    int hl = lane >> 4;
    int c4 = (lane & 15) * 4;

    float ad = adst[node * 2 + hl];

    // self loop handled analytically
    float e = asrc[node * 2 + hl] + ad;
    e = (e > 0.f) ? e : 0.2f * e;
    float p = __expf(e);
    float sum = p;
    float4 hv = *(const float4*)&h[(size_t)node * 128 + hl * 64 + c4];
    float4 acc = make_float4(hv.x * p, hv.y * p, hv.z * p, hv.w * p);

    int beg = offs[node], end = offs[node + 1];
    for (int j = beg; j < end; ++j) {
        int s = csr[j];
        float e2 = asrc[s * 2 + hl] + ad;
        e2 = (e2 > 0.f) ? e2 : 0.2f * e2;
        float p2 = __expf(e2);
        sum += p2;
        float4 hv2 = *(const float4*)&h[(size_t)s * 128 + hl * 64 + c4];
        acc.x = fmaf(hv2.x, p2, acc.x);
        acc.y = fmaf(hv2.y, p2, acc.y);
        acc.z = fmaf(hv2.z, p2, acc.z);
        acc.w = fmaf(hv2.w, p2, acc.w);
    }

    float inv = 1.f / sum;
    float4 bv = *(const float4*)&bias[hl * 64 + c4];
    float4 r;
    r.x = fmaxf(fmaf(acc.x, inv, bv.x), 0.f);
    r.y = fmaxf(fmaf(acc.y, inv, bv.y), 0.f);
    r.z = fmaxf(fmaf(acc.z, inv, bv.z), 0.f);
    r.w = fmaxf(fmaf(acc.w, inv, bv.w), 0.f);
    *(float4*)&xcomb[(size_t)node * 256 + colOff + hl * 64 + c4] = r;
}

// ---------------- launch ----------------
extern "C" void kernel_launch(void* const* d_in, const int* in_sizes, int n_in,
                              void* d_out, int out_size) {
    const float* x    = (const float*)d_in[0];
    const int*   eic  = (const int*)d_in[1];
    const int*   eil  = (const int*)d_in[2];
    const float* W1   = (const float*)d_in[3];
    const float* as1  = (const float*)d_in[4];
    const float* ad1  = (const float*)d_in[5];
    const float* b1   = (const float*)d_in[6];
    const float* W2   = (const float*)d_in[7];
    const float* as2  = (const float*)d_in[8];
    const float* ad2  = (const float*)d_in[9];
    const float* b2   = (const float*)d_in[10];
    const float* fcW  = (const float*)d_in[11];
    const float* fcb  = (const float*)d_in[12];
    float* out = (float*)d_out;

    float *h1, *h2, *xcomb, *pas1, *pad1, *pas2, *pad2;
    int *cnt, *offs, *cur, *csr;
    __nv_bfloat16 *w1, *w2, *wf;
    cudaGetSymbolAddress((void**)&h1, g_h1);
    cudaGetSymbolAddress((void**)&h2, g_h2);
    cudaGetSymbolAddress((void**)&xcomb, g_xcomb);
    cudaGetSymbolAddress((void**)&pas1, g_as1);
    cudaGetSymbolAddress((void**)&pad1, g_ad1);
    cudaGetSymbolAddress((void**)&pas2, g_as2);
    cudaGetSymbolAddress((void**)&pad2, g_ad2);
    cudaGetSymbolAddress((void**)&cnt, g_cnt);
    cudaGetSymbolAddress((void**)&offs, g_offs);
    cudaGetSymbolAddress((void**)&cur, g_cur);
    cudaGetSymbolAddress((void**)&csr, g_csr);
    cudaGetSymbolAddress((void**)&w1, g_w1);
    cudaGetSymbolAddress((void**)&w2, g_w2);
    cudaGetSymbolAddress((void**)&wf, g_wf);

    constexpr int SMEM_H = 2 * 128 * 512 + 65536;  // 196608
    constexpr int SMEM_F = 2 * 64 * 512 + 65536;   // 131072
    cudaFuncSetAttribute(gemm_mma_kernel<128, false>,
                         cudaFuncAttributeMaxDynamicSharedMemorySize, SMEM_H);
    cudaFuncSetAttribute(gemm_mma_kernel<64, true>,
                         cudaFuncAttributeMaxDynamicSharedMemorySize, SMEM_F);

    const int numTiles = (NN + 127) / 128;  // 782

    // weight prep (tiny)
    prep_w_kernel<<<320, 256>>>(W1, W2, fcW, w1, w2, wf);

    // CSR build for both layers (fused)
    cudaMemsetAsync(cnt, 0, 2 * NN * sizeof(int));
    count2_kernel<<<(2 * EE + 255) / 256, 256>>>(eic, eil, cnt);
    scan2_kernel<<<2, 1024>>>(cnt, offs, cur);
    fill2_kernel<<<(2 * EE + 255) / 256, 256>>>(eic, eil, cur, csr);

    // feature transforms (tensor-core, 3-product hi/lo compensated)
    gemm_mma_kernel<128, false><<<148, 256, SMEM_H>>>(x, w1, nullptr, h1, NN, numTiles);
    gemm_mma_kernel<128, false><<<148, 256, SMEM_H>>>(x, w2, nullptr, h2, NN, numTiles);

    // attention coefficients
    acoef_kernel<<<(NN * 32 + 255) / 256, 256>>>(h1, h2, as1, ad1, as2, ad2,
                                                 pas1, pad1, pas2, pad2);

    // aggregation (single pass, analytic self loop)
    const int aggBlocks = (NN * 32 + 255) / 256;
    agg_kernel<<<aggBlocks, 256>>>(h1, pas1, pad1, offs, csr, b1, xcomb, 0);
    agg_kernel<<<aggBlocks, 256>>>(h2, pas2, pad2, offs + (NN + 1), csr + EE, b2,
                                   xcomb, 128);

    // final FC (tensor-core)
    gemm_mma_kernel<64, true><<<148, 256, SMEM_F>>>(xcomb, wf, fcb, out, NN, numTiles);
}

// round 14
// speedup vs baseline: 1.7286x; 1.0639x over previous
#include <cuda_runtime.h>
#include <cuda_bf16.h>
#include <cuda_fp16.h>
#include <cstdint>

#define NN 100000
#define EE 1600000
#define NTILES 782          // ceil(NN/128)

// ---------------- scratch (no allocation allowed) ----------------
__device__ __half g_h1[NN * 128];
__device__ __half g_h2[NN * 128];
__device__ float  g_xcomb[NN * 256];
__device__ float  g_as1[NN * 2];
__device__ float  g_ad1[NN * 2];
__device__ float  g_as2[NN * 2];
__device__ float  g_ad2[NN * 2];
__device__ int    g_cnt[2 * NN];
__device__ int    g_offs[2 * (NN + 1)];
__device__ int    g_cur[2 * NN];
__device__ int    g_csr[2 * EE];
// pre-split, pre-swizzled x images: per tile, per 64-k chunk: hi 16KB + lo 16KB
__device__ uint4  g_xs[NTILES * 8192];
// W^T bf16 hi image + lo image (swizzled, chunk-major)
__device__ __align__(16) __nv_bfloat16 g_w1[128 * 512];
__device__ __align__(16) __nv_bfloat16 g_w2[128 * 512];
__device__ __align__(16) __nv_bfloat16 g_wf[64 * 512];

// ---------------- helpers ----------------
__device__ __forceinline__ uint32_t smem_to_u32(const void* p) {
    uint32_t a;
    asm("{ .reg .u64 t; cvta.to.shared.u64 t, %1; cvt.u32.u64 %0, t; }" : "=r"(a) : "l"(p));
    return a;
}
__device__ __forceinline__ void ldmatrix_x4(uint32_t* r, uint32_t addr) {
    asm volatile("ldmatrix.sync.aligned.m8n8.x4.shared.b16 {%0,%1,%2,%3}, [%4];"
        : "=r"(r[0]), "=r"(r[1]), "=r"(r[2]), "=r"(r[3]) : "r"(addr));
}
__device__ __forceinline__ void ldmatrix_x2(uint32_t* r, uint32_t addr) {
    asm volatile("ldmatrix.sync.aligned.m8n8.x2.shared.b16 {%0,%1}, [%2];"
        : "=r"(r[0]), "=r"(r[1]) : "r"(addr));
}
__device__ __forceinline__ void mma16816(float* c, const uint32_t* a, const uint32_t* b) {
    asm volatile(
        "mma.sync.aligned.m16n8k16.row.col.f32.bf16.bf16.f32 "
        "{%0,%1,%2,%3},{%4,%5,%6,%7},{%8,%9},{%0,%1,%2,%3};"
        : "+f"(c[0]), "+f"(c[1]), "+f"(c[2]), "+f"(c[3])
        : "r"(a[0]), "r"(a[1]), "r"(a[2]), "r"(a[3]), "r"(b[0]), "r"(b[1]));
}
__device__ __forceinline__ void cp_async16(uint32_t dst, const void* src) {
    asm volatile("cp.async.cg.shared.global [%0], [%1], 16;" :: "r"(dst), "l"(src));
}
#define CP_COMMIT() asm volatile("cp.async.commit_group;")
#define CP_WAIT(n)  asm volatile("cp.async.wait_group %0;" :: "n"(n))
__device__ __forceinline__ uint32_t bf2bits(__nv_bfloat162 v) {
    return *reinterpret_cast<uint32_t*>(&v);
}
__device__ __forceinline__ uint32_t bfpack(float a, float b) {
    __nv_bfloat162 t = __halves2bfloat162(__float2bfloat16_rn(a), __float2bfloat16_rn(b));
    return *reinterpret_cast<uint32_t*>(&t);
}

// ================= phase1: prep_x + count + prep_w (fused) =================
#define PX_BLOCKS 12512     // 782*4*128*8 / 256
#define CNT_BLOCKS 12500    // 2*EE / 256
#define PW_BLOCKS 320       // 81920 / 256

__global__ __launch_bounds__(256) void phase1_kernel(
    const float* __restrict__ x,
    const int* __restrict__ eic, const int* __restrict__ eil,
    const float* __restrict__ W1, const float* __restrict__ W2,
    const float* __restrict__ Wf,
    uint4* __restrict__ xs,
    __nv_bfloat16* __restrict__ o1, __nv_bfloat16* __restrict__ o2,
    __nv_bfloat16* __restrict__ of,
    int* __restrict__ cnt)
{
    const int b = blockIdx.x, tid = threadIdx.x;
    if (b < PX_BLOCKS) {
        // ---- pre-split x into swizzled bf16 hi/lo tile images ----
        int id = b * 256 + tid;
        int u = id & 7, r = (id >> 3) & 127, kc = (id >> 10) & 3, tile = id >> 12;
        int gm = tile * 128 + r;
        float4 v0 = make_float4(0.f, 0.f, 0.f, 0.f), v1 = v0;
        if (gm < NN) {
            const float* src = &x[(size_t)gm * 256 + kc * 64 + u * 8];
            v0 = *(const float4*)src;
            v1 = *(const float4*)(src + 4);
        }
        float f[8] = {v0.x, v0.y, v0.z, v0.w, v1.x, v1.y, v1.z, v1.w};
        uint32_t hi[4], lo[4];
#pragma unroll
        for (int q = 0; q < 4; q++) {
            __nv_bfloat16 ha = __float2bfloat16_rn(f[2 * q]);
            __nv_bfloat16 hb = __float2bfloat16_rn(f[2 * q + 1]);
            __nv_bfloat162 hp = __halves2bfloat162(ha, hb);
            hi[q] = *reinterpret_cast<uint32_t*>(&hp);
            lo[q] = bfpack(f[2 * q] - __bfloat162float(ha),
                           f[2 * q + 1] - __bfloat162float(hb));
        }
        int unit = r * 8 + (u ^ (r & 7));
        uint4* base = xs + (size_t)tile * 8192 + kc * 2048;
        base[unit]        = make_uint4(hi[0], hi[1], hi[2], hi[3]);
        base[1024 + unit] = make_uint4(lo[0], lo[1], lo[2], lo[3]);
    } else if (b < PX_BLOCKS + CNT_BLOCKS) {
        // ---- count incoming edges (both layers) ----
        int j = (b - PX_BLOCKS) * 256 + tid;
        if (j < EE)          atomicAdd(&cnt[eic[EE + j]], 1);
        else                 atomicAdd(&cnt[NN + eil[EE + (j - EE)]], 1);
    } else {
        // ---- prep weights: hi/lo swizzled images ----
        int id = (b - PX_BLOCKS - CNT_BLOCKS) * 256 + tid;
        const float* W; __nv_bfloat16* o; int NF, li;
        if (id < 32768)      { W = W1; o = o1; NF = 128; li = id; }
        else if (id < 65536) { W = W2; o = o2; NF = 128; li = id - 32768; }
        else                 { W = Wf; o = of; NF = 64;  li = id - 65536; }
        int n = li % NF, k = li / NF;
        float v = W[li];
        __nv_bfloat16 hv = __float2bfloat16_rn(v);
        __nv_bfloat16 lv = __float2bfloat16_rn(v - __bfloat162float(hv));
        uint32_t off = (uint32_t)((k >> 6) * NF + n) * 128u
                     + (uint32_t)((((k & 63) >> 3) ^ (n & 7)) << 4)
                     + (uint32_t)(k & 7) * 2u;
        *(__nv_bfloat16*)((char*)o + off) = hv;
        *(__nv_bfloat16*)((char*)(o + NF * 256) + off) = lv;
    }
}

// ================= scan (exclusive prefix per layer) =================
__global__ __launch_bounds__(1024) void scan2_kernel(
    const int* __restrict__ cntA, int* __restrict__ offsA, int* __restrict__ curA)
{
    const int L = blockIdx.x;
    const int* cnt = cntA + L * NN;
    int* offs = offsA + L * (NN + 1);
    int* cur  = curA + L * NN;

    __shared__ int sums[1024];
    const int CH = (NN + 1023) / 1024;
    int t = threadIdx.x;
    int base = t * CH;
    int local = 0;
    for (int i = 0; i < CH; i++) {
        int idx = base + i;
        if (idx < NN) local += cnt[idx];
    }
    sums[t] = local;
    __syncthreads();
#pragma unroll
    for (int off = 1; off < 1024; off <<= 1) {
        int v = (t >= off) ? sums[t - off] : 0;
        __syncthreads();
        sums[t] += v;
        __syncthreads();
    }
    int run = sums[t] - local;
    for (int i = 0; i < CH; i++) {
        int idx = base + i;
        if (idx < NN) {
            offs[idx] = run;
            cur[idx] = run;
            run += cnt[idx];
        }
    }
    if (base < NN && base + CH >= NN) offs[NN] = run;
}

// ================= h-GEMM: both layers, pre-split A via cp.async =================
// 148 CTAs: even -> layer1, odd -> layer2 (74 CTAs each, strided tiles).
// C = Ahi*Whi + Ahi*Wlo + Alo*Whi, fp32 acc, output fp16.
__global__ __launch_bounds__(256) void gemm_h_kernel(
    const uint4* __restrict__ xs,
    const __nv_bfloat16* __restrict__ w1, const __nv_bfloat16* __restrict__ w2,
    __half* __restrict__ h1, __half* __restrict__ h2)
{
    constexpr int NF = 128, NT = 8;
    constexpr int OFF_A = 131072;         // after 2 W images (64KB each)

    extern __shared__ __align__(16) char smem[];
    const uint32_t sb = smem_to_u32(smem);
    const int tid = threadIdx.x, wid = tid >> 5, lane = tid & 31;
    const int wm = wid & 3, wn = wid >> 2;
    const int wnb = wn * 64;

    const int half_ = blockIdx.x & 1;
    const int cidx = blockIdx.x >> 1;     // 0..73
    const __nv_bfloat16* Wt = half_ ? w2 : w1;
    __half* H = half_ ? h2 : h1;

    // W images -> smem once
    for (int i = tid; i < 8192; i += 256)
        cp_async16(sb + (uint32_t)i * 16u, ((const uint4*)Wt) + i);
    CP_COMMIT();
    CP_WAIT(0);
    __syncthreads();

    const int r15 = lane & 15, rh = lane >> 4;

    auto issueA = [&](int tile, int kc, int buf) {
        uint32_t dst = sb + OFF_A + (uint32_t)buf * 32768u;
        const uint4* src = xs + (size_t)tile * 8192 + kc * 2048;
#pragma unroll
        for (int i = 0; i < 8; i++)
            cp_async16(dst + (uint32_t)(i * 256 + tid) * 16u, src + i * 256 + tid);
        CP_COMMIT();
    };

    auto mmaChunk = [&](int kc, int buf, float acc[2][NT][4]) {
        const uint32_t aH = sb + OFF_A + (uint32_t)buf * 32768u;
        const uint32_t aL = aH + 16384u;
        const uint32_t bH = sb + (uint32_t)kc * 16384u;
        const uint32_t bL = bH + 65536u;
#pragma unroll
        for (int k16 = 0; k16 < 4; k16++) {
            uint32_t ah[2][4], al[2][4];
#pragma unroll
            for (int mt = 0; mt < 2; mt++) {
                int row = wm * 32 + mt * 16 + r15;
                uint32_t off = (uint32_t)row * 128u +
                               (uint32_t)(((k16 * 2 + rh) ^ (row & 7)) << 4);
                ldmatrix_x4(ah[mt], aH + off);
                ldmatrix_x4(al[mt], aL + off);
            }
#pragma unroll
            for (int nt = 0; nt < NT; nt++) {
                int rn = wnb + nt * 8 + (lane & 7);
                int un = k16 * 2 + ((lane >> 3) & 1);
                uint32_t off = (uint32_t)rn * 128u + (uint32_t)((un ^ (rn & 7)) << 4);
                uint32_t bh[2], bl[2];
                ldmatrix_x2(bh, bH + off);
                ldmatrix_x2(bl, bL + off);
#pragma unroll
                for (int mt = 0; mt < 2; mt++) {
                    mma16816(acc[mt][nt], ah[mt], bh);
                    mma16816(acc[mt][nt], ah[mt], bl);
                    mma16816(acc[mt][nt], al[mt], bh);
                }
            }
        }
    };

    int tile = cidx;
    if (tile < NTILES) { issueA(tile, 0, 0); issueA(tile, 1, 1); }

    for (; tile < NTILES; tile += 74) {
        const int m0 = tile * 128;
        const int nxt = tile + 74;
        const bool hasNext = (nxt < NTILES);
        float acc[2][NT][4];
#pragma unroll
        for (int mt = 0; mt < 2; mt++)
#pragma unroll
            for (int nt = 0; nt < NT; nt++)
#pragma unroll
                for (int q = 0; q < 4; q++) acc[mt][nt][q] = 0.f;

        // kc = 0
        CP_WAIT(1); __syncthreads();
        mmaChunk(0, 0, acc); __syncthreads();
        issueA(tile, 2, 0);
        // kc = 1
        CP_WAIT(1); __syncthreads();
        mmaChunk(1, 1, acc); __syncthreads();
        issueA(tile, 3, 1);
        // kc = 2
        CP_WAIT(1); __syncthreads();
        mmaChunk(2, 0, acc); __syncthreads();
        if (hasNext) issueA(nxt, 0, 0);
        // kc = 3
        if (hasNext) { CP_WAIT(1); } else { CP_WAIT(0); }
        __syncthreads();
        mmaChunk(3, 1, acc); __syncthreads();
        if (hasNext) issueA(nxt, 1, 1);

        // epilogue: fp32 acc -> fp16 stores
#pragma unroll
        for (int nt = 0; nt < NT; nt++) {
            int col = wnb + nt * 8 + (lane & 3) * 2;
#pragma unroll
            for (int mt = 0; mt < 2; mt++) {
                int row = m0 + wm * 32 + mt * 16 + (lane >> 2);
                if (row < NN) {
                    __half2 v = __floats2half2_rn(acc[mt][nt][0], acc[mt][nt][1]);
                    *(__half2*)&H[(size_t)row * 128 + col] = v;
                }
                if (row + 8 < NN) {
                    __half2 v = __floats2half2_rn(acc[mt][nt][2], acc[mt][nt][3]);
                    *(__half2*)&H[(size_t)(row + 8) * 128 + col] = v;
                }
            }
        }
    }
}

// ================= phase3: fill CSR + attention coefficients (fused) =================
__global__ __launch_bounds__(256) void phase3_kernel(
    const int* __restrict__ eic, const int* __restrict__ eil,
    int* __restrict__ cur, int* __restrict__ csr,
    const __half* __restrict__ h1, const __half* __restrict__ h2,
    const float* __restrict__ as1, const float* __restrict__ ad1,
    const float* __restrict__ as2, const float* __restrict__ ad2,
    float* __restrict__ oas1, float* __restrict__ oad1,
    float* __restrict__ oas2, float* __restrict__ oad2)
{
    const int b = blockIdx.x, tid = threadIdx.x;
    if (b < CNT_BLOCKS) {
        int j = b * 256 + tid;
        const int* ei; int* cu; int* cs; int e;
        if (j < EE) { ei = eic; cu = cur;      cs = csr;      e = j; }
        else        { ei = eil; cu = cur + NN; cs = csr + EE; e = j - EE; }
        int s = ei[e], d = ei[EE + e];
        int pos = atomicAdd(&cu[d], 1);
        cs[pos] = s;
    } else {
        int node = ((b - CNT_BLOCKS) * 256 + tid) >> 5;
        if (node >= NN) return;
        int lane = tid & 31;
        int hl = lane >> 4;
#pragma unroll
        for (int L = 0; L < 2; L++) {
            const __half* h = (L == 0) ? h1 : h2;
            const float* ats = (L == 0) ? as1 : as2;
            const float* atd = (L == 0) ? ad1 : ad2;
            float* oas = (L == 0) ? oas1 : oas2;
            float* oad = (L == 0) ? oad1 : oad2;

            uint2 raw = *(const uint2*)&h[(size_t)node * 128 + lane * 4];
            float2 f0 = __half22float2(*(__half2*)&raw.x);
            float2 f1 = __half22float2(*(__half2*)&raw.y);
            float4 sv = *(const float4*)&ats[lane * 4];
            float4 dv = *(const float4*)&atd[lane * 4];
            float ps = f0.x * sv.x + f0.y * sv.y + f1.x * sv.z + f1.y * sv.w;
            float pd = f0.x * dv.x + f0.y * dv.y + f1.x * dv.z + f1.y * dv.w;
#pragma unroll
            for (int o = 8; o > 0; o >>= 1) {
                ps += __shfl_xor_sync(0xffffffffu, ps, o);
                pd += __shfl_xor_sync(0xffffffffu, pd, o);
            }
            if ((lane & 15) == 0) {
                oas[node * 2 + hl] = ps;
                oad[node * 2 + hl] = pd;
            }
        }
    }
}

// ================= aggregation: both layers, one warp per dst =================
__global__ __launch_bounds__(256) void agg2_kernel(
    const __half* __restrict__ h1, const __half* __restrict__ h2,
    const float* __restrict__ pas1, const float* __restrict__ pad1,
    const float* __restrict__ pas2, const float* __restrict__ pad2,
    const int* __restrict__ offsA, const int* __restrict__ csrA,
    const float* __restrict__ b1, const float* __restrict__ b2,
    float* __restrict__ xcomb)
{
    int g = blockIdx.x * 8 + (threadIdx.x >> 5);
    int layer = (g >= NN);
    int node = g - layer * NN;
    int lane = threadIdx.x & 31;
    int hl = lane >> 4;
    int c4 = (lane & 15) * 4;

    const __half* h   = layer ? h2 : h1;
    const float* asrc = layer ? pas2 : pas1;
    const float* adst = layer ? pad2 : pad1;
    const int* offs   = offsA + layer * (NN + 1);
    const int* csr    = csrA + layer * EE;
    const float* bias = layer ? b2 : b1;
    const int colOff  = layer * 128;

    float ad = adst[node * 2 + hl];

    // self loop (analytic)
    float e = asrc[node * 2 + hl] + ad;
    e = (e > 0.f) ? e : 0.2f * e;
    float p = __expf(e);
    float sum = p;
    uint2 raw = *(const uint2*)&h[(size_t)node * 128 + hl * 64 + c4];
    float2 f0 = __half22float2(*(__half2*)&raw.x);
    float2 f1 = __half22float2(*(__half2*)&raw.y);
    float4 acc = make_float4(f0.x * p, f0.y * p, f1.x * p, f1.y * p);

    int beg = offs[node], end = offs[node + 1];
    for (int j = beg; j < end; ++j) {
        int s = csr[j];
        float e2 = asrc[s * 2 + hl] + ad;
        e2 = (e2 > 0.f) ? e2 : 0.2f * e2;
        float p2 = __expf(e2);
        sum += p2;
        uint2 r2 = *(const uint2*)&h[(size_t)s * 128 + hl * 64 + c4];
        float2 g0 = __half22float2(*(__half2*)&r2.x);
        float2 g1 = __half22float2(*(__half2*)&r2.y);
        acc.x = fmaf(g0.x, p2, acc.x);
        acc.y = fmaf(g0.y, p2, acc.y);
        acc.z = fmaf(g1.x, p2, acc.z);
        acc.w = fmaf(g1.y, p2, acc.w);
    }

    float inv = 1.f / sum;
    float4 bv = *(const float4*)&bias[hl * 64 + c4];
    float4 r;
    r.x = fmaxf(fmaf(acc.x, inv, bv.x), 0.f);
    r.y = fmaxf(fmaf(acc.y, inv, bv.y), 0.f);
    r.z = fmaxf(fmaf(acc.z, inv, bv.z), 0.f);
    r.w = fmaxf(fmaf(acc.w, inv, bv.w), 0.f);
    *(float4*)&xcomb[(size_t)node * 256 + colOff + hl * 64 + c4] = r;
}

// ================= FC GEMM (inline hi/lo split, NF=64) =================
__global__ __launch_bounds__(256) void gemm_fc_kernel(
    const float* __restrict__ A, const __nv_bfloat16* __restrict__ Wt,
    const float* __restrict__ bias, float* __restrict__ C, int M, int numTiles)
{
    constexpr int NF = 64, NT = 4;
    constexpr int WIMG = NF * 512;       // 32768
    constexpr int OFF_A = 2 * WIMG;      // 65536

    extern __shared__ __align__(16) char smem[];
    const uint32_t sb = smem_to_u32(smem);
    const int tid = threadIdx.x, wid = tid >> 5, lane = tid & 31;
    const int wm = wid & 3, wn = wid >> 2;
    const int wnb = wn * 32;

    for (int i = tid; i < NF * 64; i += 256)
        cp_async16(sb + (uint32_t)i * 16u, ((const uint4*)Wt) + i);
    CP_COMMIT();
    CP_WAIT(0);
    __syncthreads();

    const int r15 = lane & 15, rh = lane >> 4;
    float4 pa[8];

    for (int tile = blockIdx.x; tile < numTiles; tile += gridDim.x) {
        const int m0 = tile * 128;
        float acc[2][NT][4];
#pragma unroll
        for (int mt = 0; mt < 2; mt++)
#pragma unroll
            for (int nt = 0; nt < NT; nt++)
#pragma unroll
                for (int q = 0; q < 4; q++) acc[mt][nt][q] = 0.f;

#pragma unroll
        for (int i = 0; i < 8; i++) {
            int p = i * 256 + tid, row = p >> 4, c4 = p & 15, gm = m0 + row;
            pa[i] = (gm < M) ? *(const float4*)&A[(size_t)gm * 256 + c4 * 4]
                             : make_float4(0.f, 0.f, 0.f, 0.f);
        }

#pragma unroll
        for (int kc = 0; kc < 4; kc++) {
            const int buf = kc & 1;
            const uint32_t aOff = OFF_A + (uint32_t)buf * 32768u;
#pragma unroll
            for (int i = 0; i < 8; i++) {
                int p = i * 256 + tid, row = p >> 4, c4 = p & 15;
                float4 v = pa[i];
                __nv_bfloat16 h0 = __float2bfloat16_rn(v.x);
                __nv_bfloat16 h1 = __float2bfloat16_rn(v.y);
                __nv_bfloat16 h2 = __float2bfloat16_rn(v.z);
                __nv_bfloat16 h3 = __float2bfloat16_rn(v.w);
                int u = c4 >> 1, half = (c4 & 1) * 8;
                uint32_t base = (uint32_t)row * 128u +
                                (uint32_t)((u ^ (row & 7)) << 4) + (uint32_t)half;
                __nv_bfloat162 hp0 = __halves2bfloat162(h0, h1);
                __nv_bfloat162 hp1 = __halves2bfloat162(h2, h3);
                *(uint2*)(smem + aOff + base) =
                    make_uint2(bf2bits(hp0), bf2bits(hp1));
                *(uint2*)(smem + aOff + 16384u + base) = make_uint2(
                    bfpack(v.x - __bfloat162float(h0), v.y - __bfloat162float(h1)),
                    bfpack(v.z - __bfloat162float(h2), v.w - __bfloat162float(h3)));
            }
            __syncthreads();

            if (kc < 3) {
#pragma unroll
                for (int i = 0; i < 8; i++) {
                    int p = i * 256 + tid, row = p >> 4, c4 = p & 15, gm = m0 + row;
                    pa[i] = (gm < M)
                        ? *(const float4*)&A[(size_t)gm * 256 + (kc + 1) * 64 + c4 * 4]
                        : make_float4(0.f, 0.f, 0.f, 0.f);
                }
            }

            const uint32_t aH = sb + aOff;
            const uint32_t aL = aH + 16384u;
            const uint32_t bH = sb + (uint32_t)kc * (NF * 128u);
            const uint32_t bL = bH + (uint32_t)WIMG;
#pragma unroll
            for (int k16 = 0; k16 < 4; k16++) {
                uint32_t ah[2][4], al[2][4];
#pragma unroll
                for (int mt = 0; mt < 2; mt++) {
                    int row = wm * 32 + mt * 16 + r15;
                    uint32_t off = (uint32_t)row * 128u +
                                   (uint32_t)(((k16 * 2 + rh) ^ (row & 7)) << 4);
                    ldmatrix_x4(ah[mt], aH + off);
                    ldmatrix_x4(al[mt], aL + off);
                }
#pragma unroll
                for (int nt = 0; nt < NT; nt++) {
                    int rn = wnb + nt * 8 + (lane & 7);
                    int un = k16 * 2 + ((lane >> 3) & 1);
                    uint32_t off = (uint32_t)rn * 128u +
                                   (uint32_t)((un ^ (rn & 7)) << 4);
                    uint32_t bh[2], bl[2];
                    ldmatrix_x2(bh, bH + off);
                    ldmatrix_x2(bl, bL + off);
#pragma unroll
                    for (int mt = 0; mt < 2; mt++) {
                        mma16816(acc[mt][nt], ah[mt], bh);
                        mma16816(acc[mt][nt], ah[mt], bl);
                        mma16816(acc[mt][nt], al[mt], bh);
                    }
                }
            }
            __syncthreads();
        }

#pragma unroll
        for (int nt = 0; nt < NT; nt++) {
            int col = wnb + nt * 8 + (lane & 3) * 2;
            float bx = bias[col], by = bias[col + 1];
#pragma unroll
            for (int mt = 0; mt < 2; mt++) {
                int row = m0 + wm * 32 + mt * 16 + (lane >> 2);
                if (row < M) {
                    float2 o = make_float2(acc[mt][nt][0] + bx, acc[mt][nt][1] + by);
                    *(float2*)&C[(size_t)row * NF + col] = o;
                }
                if (row + 8 < M) {
                    float2 o = make_float2(acc[mt][nt][2] + bx, acc[mt][nt][3] + by);
                    *(float2*)&C[(size_t)(row + 8) * NF + col] = o;
                }
            }
        }
    }
}

// ---------------- launch ----------------
extern "C" void kernel_launch(void* const* d_in, const int* in_sizes, int n_in,
                              void* d_out, int out_size) {
    const float* x    = (const float*)d_in[0];
    const int*   eic  = (const int*)d_in[1];
    const int*   eil  = (const int*)d_in[2];
    const float* W1   = (const float*)d_in[3];
    const float* as1  = (const float*)d_in[4];
    const float* ad1  = (const float*)d_in[5];
    const float* b1   = (const float*)d_in[6];
    const float* W2   = (const float*)d_in[7];
    const float* as2  = (const float*)d_in[8];
    const float* ad2  = (const float*)d_in[9];
    const float* b2   = (const float*)d_in[10];
    const float* fcW  = (const float*)d_in[11];
    const float* fcb  = (const float*)d_in[12];
    float* out = (float*)d_out;

    __half *h1, *h2;
    float *xcomb, *pas1, *pad1, *pas2, *pad2;
    int *cnt, *offs, *cur, *csr;
    uint4* xs;
    __nv_bfloat16 *w1, *w2, *wf;
    cudaGetSymbolAddress((void**)&h1, g_h1);
    cudaGetSymbolAddress((void**)&h2, g_h2);
    cudaGetSymbolAddress((void**)&xcomb, g_xcomb);
    cudaGetSymbolAddress((void**)&pas1, g_as1);
    cudaGetSymbolAddress((void**)&pad1, g_ad1);
    cudaGetSymbolAddress((void**)&pas2, g_as2);
    cudaGetSymbolAddress((void**)&pad2, g_ad2);
    cudaGetSymbolAddress((void**)&cnt, g_cnt);
    cudaGetSymbolAddress((void**)&offs, g_offs);
    cudaGetSymbolAddress((void**)&cur, g_cur);
    cudaGetSymbolAddress((void**)&csr, g_csr);
    cudaGetSymbolAddress((void**)&xs, g_xs);
    cudaGetSymbolAddress((void**)&w1, g_w1);
    cudaGetSymbolAddress((void**)&w2, g_w2);
    cudaGetSymbolAddress((void**)&wf, g_wf);

    constexpr int SMEM_H = 131072 + 65536;   // 196608
    constexpr int SMEM_F = 65536 + 65536;    // 131072
    cudaFuncSetAttribute(gemm_h_kernel,
                         cudaFuncAttributeMaxDynamicSharedMemorySize, SMEM_H);
    cudaFuncSetAttribute(gemm_fc_kernel,
                         cudaFuncAttributeMaxDynamicSharedMemorySize, SMEM_F);

    // 1. zero counters
    cudaMemsetAsync(cnt, 0, 2 * NN * sizeof(int));

    // 2. phase1: pre-split x + count edges + prep weights
    phase1_kernel<<<PX_BLOCKS + CNT_BLOCKS + PW_BLOCKS, 256>>>(
        x, eic, eil, W1, W2, fcW, xs, w1, w2, wf, cnt);

    // 3. scan
    scan2_kernel<<<2, 1024>>>(cnt, offs, cur);

    // 4. both h-GEMMs in one launch
    gemm_h_kernel<<<148, 256, SMEM_H>>>(xs, w1, w2, h1, h2);

    // 5. fill CSR + attention coefficients
    phase3_kernel<<<2 * CNT_BLOCKS, 256>>>(eic, eil, cur, csr, h1, h2,
                                           as1, ad1, as2, ad2,
                                           pas1, pad1, pas2, pad2);

    // 6. aggregation (both layers)
    agg2_kernel<<<25000, 256>>>(h1, h2, pas1, pad1, pas2, pad2,
                                offs, csr, b1, b2, xcomb);

    // 7. final FC
    gemm_fc_kernel<<<148, 256, SMEM_F>>>(xcomb, wf, fcb, out, NN, NTILES);
}